// round 1
// baseline (speedup 1.0000x reference)
#include <cuda_runtime.h>
#include <cstddef>

#define NN 50000
#define EE 850000
#define FDIM 256
#define HH 4

// ---------------- scratch (static device globals; no runtime alloc) ----------
__device__ float g_h[(size_t)NN * FDIM];      // current layer h = x @ W
__device__ float g_x2[(size_t)NN * FDIM];     // layer-1 output (relu'd)
__device__ float g_el[NN * HH];
__device__ float g_er[NN * HH];
__device__ float g_den[NN * HH];
__device__ float g_w[(size_t)EE * HH];        // exp(leakyrelu(e)) per edge/head
__device__ int   g_indeg[NN];
__device__ int   g_off[NN + 1];
__device__ int   g_cur[NN];
__device__ int   g_eidx[EE];

// ---------------- CSR build ----------------
__global__ void zero_indeg_kernel() {
    int i = blockIdx.x * blockDim.x + threadIdx.x;
    if (i < NN) g_indeg[i] = 0;
}

__global__ void csr_count_kernel(const int* __restrict__ dst, int E) {
    int e = blockIdx.x * blockDim.x + threadIdx.x;
    if (e < E) atomicAdd(&g_indeg[dst[e]], 1);
}

// single-block exclusive scan over NN counts (warp-shuffle based)
__global__ void scan_kernel() {
    __shared__ int warp_sums[32];
    __shared__ int s_carry;
    int tid = threadIdx.x;
    int lane = tid & 31, wid = tid >> 5;
    if (tid == 0) s_carry = 0;
    __syncthreads();
    for (int base = 0; base < NN; base += 1024) {
        int idx = base + tid;
        int v = (idx < NN) ? g_indeg[idx] : 0;
        int x = v;
        #pragma unroll
        for (int o = 1; o < 32; o <<= 1) {
            int t = __shfl_up_sync(0xffffffffu, x, o);
            if (lane >= o) x += t;
        }
        if (lane == 31) warp_sums[wid] = x;
        __syncthreads();
        if (wid == 0) {
            int ws = warp_sums[lane];
            #pragma unroll
            for (int o = 1; o < 32; o <<= 1) {
                int t = __shfl_up_sync(0xffffffffu, ws, o);
                if (lane >= o) ws += t;
            }
            warp_sums[lane] = ws;
        }
        __syncthreads();
        int warp_excl = (wid == 0) ? 0 : warp_sums[wid - 1];
        int excl = x - v + warp_excl + s_carry;
        if (idx < NN) { g_off[idx] = excl; g_cur[idx] = excl; }
        __syncthreads();
        if (tid == 0) s_carry += warp_sums[31];
        __syncthreads();
    }
    if (threadIdx.x == 0) g_off[NN] = s_carry;
}

__global__ void csr_scatter_kernel(const int* __restrict__ dst, int E) {
    int e = blockIdx.x * blockDim.x + threadIdx.x;
    if (e < E) {
        int p = atomicAdd(&g_cur[dst[e]], 1);
        g_eidx[p] = e;
    }
}

// ---------------- GEMM: C[nrows,256] = A[nrows,256] @ W[256,256] ----------------
__global__ __launch_bounds__(256) void gemm256_kernel(
    const float* __restrict__ A, const float* __restrict__ W,
    float* __restrict__ C, int nrows)
{
    __shared__ float As[64][32];
    __shared__ float Bs[32][256];
    int tid = threadIdx.x;
    int tx = tid & 31;      // N-dir (col groups of stride 32)
    int ty = tid >> 5;      // warp id -> row group of 8
    int rowBase = blockIdx.x * 64;

    float acc[8][8];
    #pragma unroll
    for (int i = 0; i < 8; i++)
        #pragma unroll
        for (int j = 0; j < 8; j++) acc[i][j] = 0.f;

    for (int k0 = 0; k0 < 256; k0 += 32) {
        // load A tile 64x32
        #pragma unroll
        for (int p = 0; p < 2; p++) {
            int id = tid + 256 * p;
            int r = id >> 3, kk4 = (id & 7) * 4;
            float4 v = make_float4(0.f, 0.f, 0.f, 0.f);
            if (rowBase + r < nrows)
                v = *(const float4*)(A + (size_t)(rowBase + r) * 256 + k0 + kk4);
            *(float4*)(&As[r][kk4]) = v;
        }
        // load W tile 32x256
        #pragma unroll
        for (int p = 0; p < 8; p++) {
            int id = tid + 256 * p;
            int kr = id >> 6, c4 = (id & 63) * 4;
            *(float4*)(&Bs[kr][c4]) = *(const float4*)(W + (size_t)(k0 + kr) * 256 + c4);
        }
        __syncthreads();
        #pragma unroll
        for (int kk = 0; kk < 32; kk++) {
            float a[8], b[8];
            #pragma unroll
            for (int i = 0; i < 8; i++) a[i] = As[ty * 8 + i][kk];
            #pragma unroll
            for (int j = 0; j < 8; j++) b[j] = Bs[kk][tx + 32 * j];
            #pragma unroll
            for (int i = 0; i < 8; i++)
                #pragma unroll
                for (int j = 0; j < 8; j++)
                    acc[i][j] = fmaf(a[i], b[j], acc[i][j]);
        }
        __syncthreads();
    }
    #pragma unroll
    for (int i = 0; i < 8; i++) {
        int r = rowBase + ty * 8 + i;
        if (r < nrows) {
            #pragma unroll
            for (int j = 0; j < 8; j++)
                C[(size_t)r * 256 + tx + 32 * j] = acc[i][j];
        }
    }
}

// ---------------- per-node attention coefs: el/er, zero denom ----------------
__global__ __launch_bounds__(256) void attn_kernel(
    const float* __restrict__ h, const float* __restrict__ al,
    const float* __restrict__ ar)
{
    int n = blockIdx.x;
    int tid = threadIdx.x;
    float v = h[(size_t)n * 256 + tid];
    float pl = v * al[tid];
    float pr = v * ar[tid];
    #pragma unroll
    for (int o = 16; o > 0; o >>= 1) {
        pl += __shfl_xor_sync(0xffffffffu, pl, o);
        pr += __shfl_xor_sync(0xffffffffu, pr, o);
    }
    __shared__ float sl[8], sr[8];
    int wid = tid >> 5;
    if ((tid & 31) == 0) { sl[wid] = pl; sr[wid] = pr; }
    __syncthreads();
    if (tid < 4) {
        g_el[n * 4 + tid] = sl[2 * tid] + sl[2 * tid + 1];
        g_er[n * 4 + tid] = sr[2 * tid] + sr[2 * tid + 1];
        g_den[n * 4 + tid] = 0.f;
    }
}

// ---------------- edge weights + denom ----------------
__global__ void edge_w_kernel(const int* __restrict__ src,
                              const int* __restrict__ dst, int E)
{
    int e = blockIdx.x * blockDim.x + threadIdx.x;
    if (e >= E) return;
    int s = src[e], n = dst[e];
    float4 l = ((const float4*)g_el)[s];
    float4 r = ((const float4*)g_er)[n];
    float v[4] = { l.x + r.x, l.y + r.y, l.z + r.z, l.w + r.w };
    float4 w;
    float* wp = &w.x;
    #pragma unroll
    for (int h = 0; h < 4; h++) {
        float t = v[h];
        t = (t > 0.f) ? t : 0.2f * t;   // leaky_relu slope 0.2
        t = expf(t);                    // no max-shift needed (|e| small)
        wp[h] = t;
        atomicAdd(&g_den[n * 4 + h], t);
    }
    ((float4*)g_w)[e] = w;
}

// ---------------- CSR aggregation: out[n] = relu(sum alpha*h[src] + b) ------
__global__ __launch_bounds__(256) void aggregate_kernel(
    const float* __restrict__ hbuf, const int* __restrict__ src,
    const float* __restrict__ bias, float* __restrict__ out)
{
    int n = blockIdx.x;
    int tid = threadIdx.x;
    int hh = tid >> 6;
    int beg = g_off[n], end = g_off[n + 1];
    float inv = 1.f / g_den[n * 4 + hh];

    __shared__ int   s_src[128];
    __shared__ float s_a[128 * 4];

    float acc = 0.f;
    for (int base = beg; base < end; base += 128) {
        int cnt = min(128, end - base);
        __syncthreads();
        for (int i = tid; i < cnt; i += 256) {
            int eid = g_eidx[base + i];
            s_src[i] = src[eid];
            ((float4*)s_a)[i] = ((const float4*)g_w)[eid];
        }
        __syncthreads();
        int i = 0;
        for (; i + 4 <= cnt; i += 4) {
            float a0 = s_a[(i + 0) * 4 + hh];
            float a1 = s_a[(i + 1) * 4 + hh];
            float a2 = s_a[(i + 2) * 4 + hh];
            float a3 = s_a[(i + 3) * 4 + hh];
            int s0 = s_src[i], s1 = s_src[i + 1], s2 = s_src[i + 2], s3 = s_src[i + 3];
            float h0 = hbuf[(size_t)s0 * 256 + tid];
            float h1 = hbuf[(size_t)s1 * 256 + tid];
            float h2 = hbuf[(size_t)s2 * 256 + tid];
            float h3 = hbuf[(size_t)s3 * 256 + tid];
            acc += a0 * h0 + a1 * h1 + a2 * h2 + a3 * h3;
        }
        for (; i < cnt; i++)
            acc += s_a[i * 4 + hh] * hbuf[(size_t)s_src[i] * 256 + tid];
    }
    out[(size_t)n * 256 + tid] = fmaxf(acc * inv + bias[tid], 0.f);
}

// ---------------- launch ----------------
extern "C" void kernel_launch(void* const* d_in, const int* in_sizes, int n_in,
                              void* d_out, int out_size)
{
    const float* feat = (const float*)d_in[0];
    const int*   src  = (const int*)d_in[1];
    const int*   dst  = (const int*)d_in[2];
    const float* W1   = (const float*)d_in[3];
    const float* al1  = (const float*)d_in[4];
    const float* ar1  = (const float*)d_in[5];
    const float* b1   = (const float*)d_in[6];
    const float* W2   = (const float*)d_in[7];
    const float* al2  = (const float*)d_in[8];
    const float* ar2  = (const float*)d_in[9];
    const float* b2   = (const float*)d_in[10];
    float* out = (float*)d_out;
    int E = in_sizes[1];

    void* p;
    cudaGetSymbolAddress(&p, g_h);   float* h  = (float*)p;
    cudaGetSymbolAddress(&p, g_x2);  float* x2 = (float*)p;

    int egrid = (E + 255) / 256;
    int ngrid = (NN + 255) / 256;
    int ggrid = (NN + 63) / 64;

    // CSR build (same for both layers)
    zero_indeg_kernel<<<ngrid, 256>>>();
    csr_count_kernel<<<egrid, 256>>>(dst, E);
    scan_kernel<<<1, 1024>>>();
    csr_scatter_kernel<<<egrid, 256>>>(dst, E);

    // layer 1
    gemm256_kernel<<<ggrid, 256>>>(feat, W1, h, NN);
    attn_kernel<<<NN, 256>>>(h, al1, ar1);
    edge_w_kernel<<<egrid, 256>>>(src, dst, E);
    aggregate_kernel<<<NN, 256>>>(h, src, b1, x2);

    // layer 2
    gemm256_kernel<<<ggrid, 256>>>(x2, W2, h, NN);
    attn_kernel<<<NN, 256>>>(h, al2, ar2);
    edge_w_kernel<<<egrid, 256>>>(src, dst, E);
    aggregate_kernel<<<NN, 256>>>(h, src, b2, out);
}

// round 2
// speedup vs baseline: 1.3736x; 1.3736x over previous
#include <cuda_runtime.h>
#include <cuda_bf16.h>
#include <cstdint>
#include <cstddef>

#define NN 50000
#define EE 850000
#define HH 4

// ---------------- scratch (static device globals; no runtime alloc) ----------
__device__ float g_h[(size_t)NN * 256];       // current layer h = x @ W
__device__ float g_x2[(size_t)NN * 256];      // layer-1 output (relu'd)
__device__ float g_el[NN * HH];
__device__ float g_er[NN * HH];
__device__ int   g_indeg[NN];
__device__ int   g_off[NN + 1];
__device__ int   g_cur[NN];
__device__ int   g_eidx[EE];
__device__ __nv_bfloat16 g_Wthi[256 * 256];   // W split-hi, transposed [n][k]
__device__ __nv_bfloat16 g_Wtlo[256 * 256];   // W split-lo, transposed [n][k]

// ---------------- CSR build ----------------
__global__ void zero_indeg_kernel() {
    int i = blockIdx.x * blockDim.x + threadIdx.x;
    if (i < NN) g_indeg[i] = 0;
}

__global__ void csr_count_kernel(const int* __restrict__ dst, int E) {
    int e = blockIdx.x * blockDim.x + threadIdx.x;
    if (e < E) atomicAdd(&g_indeg[dst[e]], 1);
}

__global__ void scan_kernel() {
    __shared__ int warp_sums[32];
    __shared__ int s_carry;
    int tid = threadIdx.x;
    int lane = tid & 31, wid = tid >> 5;
    if (tid == 0) s_carry = 0;
    __syncthreads();
    for (int base = 0; base < NN; base += 1024) {
        int idx = base + tid;
        int v = (idx < NN) ? g_indeg[idx] : 0;
        int x = v;
        #pragma unroll
        for (int o = 1; o < 32; o <<= 1) {
            int t = __shfl_up_sync(0xffffffffu, x, o);
            if (lane >= o) x += t;
        }
        if (lane == 31) warp_sums[wid] = x;
        __syncthreads();
        if (wid == 0) {
            int ws = warp_sums[lane];
            #pragma unroll
            for (int o = 1; o < 32; o <<= 1) {
                int t = __shfl_up_sync(0xffffffffu, ws, o);
                if (lane >= o) ws += t;
            }
            warp_sums[lane] = ws;
        }
        __syncthreads();
        int warp_excl = (wid == 0) ? 0 : warp_sums[wid - 1];
        int excl = x - v + warp_excl + s_carry;
        if (idx < NN) { g_off[idx] = excl; g_cur[idx] = excl; }
        __syncthreads();
        if (tid == 0) s_carry += warp_sums[31];
        __syncthreads();
    }
    if (threadIdx.x == 0) g_off[NN] = s_carry;
}

__global__ void csr_scatter_kernel(const int* __restrict__ dst, int E) {
    int e = blockIdx.x * blockDim.x + threadIdx.x;
    if (e < E) {
        int p = atomicAdd(&g_cur[dst[e]], 1);
        g_eidx[p] = e;
    }
}

// ---------------- W split + transpose: W[k][n] fp32 -> Wt{hi,lo}[n][k] bf16 --
__global__ void wsplit_kernel(const float* __restrict__ W) {
    int idx = blockIdx.x * 256 + threadIdx.x;     // 65536 elements
    int k = idx >> 8, n = idx & 255;
    float v = W[k * 256 + n];
    __nv_bfloat16 hi = __float2bfloat16_rn(v);
    __nv_bfloat16 lo = __float2bfloat16_rn(v - __bfloat162float(hi));
    g_Wthi[n * 256 + k] = hi;
    g_Wtlo[n * 256 + k] = lo;
}

// ---------------- bf16x3 tensor-core GEMM: C[nrows,256] = A @ W ---------------
// BM=128, BN=64, BK=32; 128 threads = 4 warps; warp tile 32(m) x 64(n).
#define SA 40
#define SB 40

__device__ __forceinline__ void mma_bf16(float* c, const uint32_t* a,
                                         uint32_t b0, uint32_t b1) {
    asm volatile(
        "mma.sync.aligned.m16n8k16.row.col.f32.bf16.bf16.f32 "
        "{%0,%1,%2,%3}, {%4,%5,%6,%7}, {%8,%9}, {%0,%1,%2,%3};"
        : "+f"(c[0]), "+f"(c[1]), "+f"(c[2]), "+f"(c[3])
        : "r"(a[0]), "r"(a[1]), "r"(a[2]), "r"(a[3]), "r"(b0), "r"(b1));
}

__device__ __forceinline__ uint32_t pack_bf16(__nv_bfloat16 lo, __nv_bfloat16 hi) {
    return ((uint32_t)__bfloat16_as_ushort(hi) << 16) | __bfloat16_as_ushort(lo);
}

__global__ __launch_bounds__(128) void gemm_bf16x3_kernel(
    const float* __restrict__ A, float* __restrict__ C, int nrows)
{
    __shared__ __nv_bfloat16 Ash[128 * SA];
    __shared__ __nv_bfloat16 Asl[128 * SA];
    __shared__ __nv_bfloat16 Bsh[64 * SB];
    __shared__ __nv_bfloat16 Bsl[64 * SB];

    int tid = threadIdx.x;
    int lane = tid & 31;
    int wid = tid >> 5;                 // 0..3 -> m offset wid*32
    int rowBase = blockIdx.x * 128;
    int nbase = blockIdx.y * 64;
    int g = lane >> 2, t = lane & 3;
    int mbase = wid * 32;

    float acc[2][8][4];
    #pragma unroll
    for (int mt = 0; mt < 2; mt++)
        #pragma unroll
        for (int nt = 0; nt < 8; nt++)
            #pragma unroll
            for (int q = 0; q < 4; q++) acc[mt][nt][q] = 0.f;

    for (int k0 = 0; k0 < 256; k0 += 32) {
        // ---- stage A: 128x32 fp32 -> split bf16 (coalesced float4 loads)
        #pragma unroll
        for (int p = 0; p < 8; p++) {
            int i = tid + p * 128;       // 0..1023 float4 slots
            int r = i >> 3, kq = (i & 7) * 4;
            float4 v = make_float4(0.f, 0.f, 0.f, 0.f);
            if (rowBase + r < nrows)
                v = *(const float4*)(A + (size_t)(rowBase + r) * 256 + k0 + kq);
            __nv_bfloat16 h0 = __float2bfloat16_rn(v.x);
            __nv_bfloat16 h1 = __float2bfloat16_rn(v.y);
            __nv_bfloat16 h2 = __float2bfloat16_rn(v.z);
            __nv_bfloat16 h3 = __float2bfloat16_rn(v.w);
            __nv_bfloat16 l0 = __float2bfloat16_rn(v.x - __bfloat162float(h0));
            __nv_bfloat16 l1 = __float2bfloat16_rn(v.y - __bfloat162float(h1));
            __nv_bfloat16 l2 = __float2bfloat16_rn(v.z - __bfloat162float(h2));
            __nv_bfloat16 l3 = __float2bfloat16_rn(v.w - __bfloat162float(h3));
            *(uint2*)&Ash[r * SA + kq] = make_uint2(pack_bf16(h0, h1), pack_bf16(h2, h3));
            *(uint2*)&Asl[r * SA + kq] = make_uint2(pack_bf16(l0, l1), pack_bf16(l2, l3));
        }
        // ---- stage B: Wt[n][k] bf16, tile 64n x 32k
        {
            int n = tid >> 1, kh = (tid & 1) * 16;
            const uint4* ph = (const uint4*)(g_Wthi + (size_t)(nbase + n) * 256 + k0 + kh);
            const uint4* pl = (const uint4*)(g_Wtlo + (size_t)(nbase + n) * 256 + k0 + kh);
            uint4 vh0 = ph[0], vh1 = ph[1];
            uint4 vl0 = pl[0], vl1 = pl[1];
            *(uint4*)&Bsh[n * SB + kh] = vh0;
            *(uint4*)&Bsh[n * SB + kh + 8] = vh1;
            *(uint4*)&Bsl[n * SB + kh] = vl0;
            *(uint4*)&Bsl[n * SB + kh + 8] = vl1;
        }
        __syncthreads();

        #pragma unroll
        for (int kk = 0; kk < 2; kk++) {
            int ks = kk * 16;
            uint32_t ah[2][4], al[2][4];
            #pragma unroll
            for (int mt = 0; mt < 2; mt++) {
                int r0 = (mbase + mt * 16 + g) * SA;
                int r1 = (mbase + mt * 16 + g + 8) * SA;
                ah[mt][0] = *(const uint32_t*)&Ash[r0 + ks + 2 * t];
                ah[mt][1] = *(const uint32_t*)&Ash[r1 + ks + 2 * t];
                ah[mt][2] = *(const uint32_t*)&Ash[r0 + ks + 2 * t + 8];
                ah[mt][3] = *(const uint32_t*)&Ash[r1 + ks + 2 * t + 8];
                al[mt][0] = *(const uint32_t*)&Asl[r0 + ks + 2 * t];
                al[mt][1] = *(const uint32_t*)&Asl[r1 + ks + 2 * t];
                al[mt][2] = *(const uint32_t*)&Asl[r0 + ks + 2 * t + 8];
                al[mt][3] = *(const uint32_t*)&Asl[r1 + ks + 2 * t + 8];
            }
            #pragma unroll
            for (int nt = 0; nt < 8; nt++) {
                int nb = (nt * 8 + g) * SB;
                uint32_t bh0 = *(const uint32_t*)&Bsh[nb + ks + 2 * t];
                uint32_t bh1 = *(const uint32_t*)&Bsh[nb + ks + 2 * t + 8];
                uint32_t bl0 = *(const uint32_t*)&Bsl[nb + ks + 2 * t];
                uint32_t bl1 = *(const uint32_t*)&Bsl[nb + ks + 2 * t + 8];
                #pragma unroll
                for (int mt = 0; mt < 2; mt++) {
                    mma_bf16(acc[mt][nt], ah[mt], bh0, bh1);
                    mma_bf16(acc[mt][nt], ah[mt], bl0, bl1);
                    mma_bf16(acc[mt][nt], al[mt], bh0, bh1);
                }
            }
        }
        __syncthreads();
    }

    // ---- epilogue: direct global stores
    #pragma unroll
    for (int mt = 0; mt < 2; mt++) {
        int r0 = rowBase + mbase + mt * 16 + g;
        int r1 = r0 + 8;
        #pragma unroll
        for (int nt = 0; nt < 8; nt++) {
            int col = nbase + nt * 8 + 2 * t;
            if (r0 < nrows)
                *(float2*)(C + (size_t)r0 * 256 + col) =
                    make_float2(acc[mt][nt][0], acc[mt][nt][1]);
            if (r1 < nrows)
                *(float2*)(C + (size_t)r1 * 256 + col) =
                    make_float2(acc[mt][nt][2], acc[mt][nt][3]);
        }
    }
}

// ---------------- per-node attention coefs: el/er ----------------
__global__ __launch_bounds__(256) void attn_kernel(
    const float* __restrict__ h, const float* __restrict__ al,
    const float* __restrict__ ar)
{
    int n = blockIdx.x;
    int tid = threadIdx.x;
    float v = h[(size_t)n * 256 + tid];
    float pl = v * al[tid];
    float pr = v * ar[tid];
    #pragma unroll
    for (int o = 16; o > 0; o >>= 1) {
        pl += __shfl_xor_sync(0xffffffffu, pl, o);
        pr += __shfl_xor_sync(0xffffffffu, pr, o);
    }
    __shared__ float sl[8], sr[8];
    int wid = tid >> 5;
    if ((tid & 31) == 0) { sl[wid] = pl; sr[wid] = pr; }
    __syncthreads();
    if (tid < 4) {
        g_el[n * 4 + tid] = sl[2 * tid] + sl[2 * tid + 1];
        g_er[n * 4 + tid] = sr[2 * tid] + sr[2 * tid + 1];
    }
}

// ---------- fused edge-softmax + CSR aggregation: out = relu(agg + b) --------
__global__ __launch_bounds__(256) void aggregate_kernel(
    const float* __restrict__ hbuf, const int* __restrict__ src,
    const float* __restrict__ bias, float* __restrict__ out)
{
    int n = blockIdx.x;
    int tid = threadIdx.x;
    int hh = tid >> 6;
    int beg = g_off[n], end = g_off[n + 1];

    __shared__ int   s_src[128];
    __shared__ float s_a[128 * 4];

    float4 rn = ((const float4*)g_er)[n];
    float acc = 0.f, den = 0.f;

    for (int base = beg; base < end; base += 128) {
        int cnt = min(128, end - base);
        __syncthreads();
        for (int i = tid; i < cnt; i += 256) {
            int eid = g_eidx[base + i];
            int s = src[eid];
            s_src[i] = s;
            float4 l = ((const float4*)g_el)[s];
            float4 w;
            float e0 = l.x + rn.x; e0 = (e0 > 0.f) ? e0 : 0.2f * e0; w.x = __expf(e0);
            float e1 = l.y + rn.y; e1 = (e1 > 0.f) ? e1 : 0.2f * e1; w.y = __expf(e1);
            float e2 = l.z + rn.z; e2 = (e2 > 0.f) ? e2 : 0.2f * e2; w.z = __expf(e2);
            float e3 = l.w + rn.w; e3 = (e3 > 0.f) ? e3 : 0.2f * e3; w.w = __expf(e3);
            ((float4*)s_a)[i] = w;
        }
        __syncthreads();
        int i = 0;
        for (; i + 4 <= cnt; i += 4) {
            float a0 = s_a[(i + 0) * 4 + hh];
            float a1 = s_a[(i + 1) * 4 + hh];
            float a2 = s_a[(i + 2) * 4 + hh];
            float a3 = s_a[(i + 3) * 4 + hh];
            int s0 = s_src[i], s1 = s_src[i + 1], s2 = s_src[i + 2], s3 = s_src[i + 3];
            float h0 = hbuf[(size_t)s0 * 256 + tid];
            float h1 = hbuf[(size_t)s1 * 256 + tid];
            float h2 = hbuf[(size_t)s2 * 256 + tid];
            float h3 = hbuf[(size_t)s3 * 256 + tid];
            acc += a0 * h0 + a1 * h1 + a2 * h2 + a3 * h3;
            den += (a0 + a1) + (a2 + a3);
        }
        for (; i < cnt; i++) {
            float a = s_a[i * 4 + hh];
            acc += a * hbuf[(size_t)s_src[i] * 256 + tid];
            den += a;
        }
    }
    out[(size_t)n * 256 + tid] = fmaxf(acc / den + bias[tid], 0.f);
}

// ---------------- launch ----------------
extern "C" void kernel_launch(void* const* d_in, const int* in_sizes, int n_in,
                              void* d_out, int out_size)
{
    const float* feat = (const float*)d_in[0];
    const int*   src  = (const int*)d_in[1];
    const int*   dst  = (const int*)d_in[2];
    const float* W1   = (const float*)d_in[3];
    const float* al1  = (const float*)d_in[4];
    const float* ar1  = (const float*)d_in[5];
    const float* b1   = (const float*)d_in[6];
    const float* W2   = (const float*)d_in[7];
    const float* al2  = (const float*)d_in[8];
    const float* ar2  = (const float*)d_in[9];
    const float* b2   = (const float*)d_in[10];
    float* out = (float*)d_out;
    int E = in_sizes[1];

    void* p;
    cudaGetSymbolAddress(&p, g_h);   float* h  = (float*)p;
    cudaGetSymbolAddress(&p, g_x2);  float* x2 = (float*)p;

    int egrid = (E + 255) / 256;
    int ngrid = (NN + 255) / 256;
    dim3 ggrid((NN + 127) / 128, 4);

    // CSR build (same for both layers)
    zero_indeg_kernel<<<ngrid, 256>>>();
    csr_count_kernel<<<egrid, 256>>>(dst, E);
    scan_kernel<<<1, 1024>>>();
    csr_scatter_kernel<<<egrid, 256>>>(dst, E);

    // layer 1
    wsplit_kernel<<<256, 256>>>(W1);
    gemm_bf16x3_kernel<<<ggrid, 128>>>(feat, h, NN);
    attn_kernel<<<NN, 256>>>(h, al1, ar1);
    aggregate_kernel<<<NN, 256>>>(h, src, b1, x2);

    // layer 2
    wsplit_kernel<<<256, 256>>>(W2);
    gemm_bf16x3_kernel<<<ggrid, 128>>>(x2, W2 ? h : h, NN);
    attn_kernel<<<NN, 256>>>(h, al2, ar2);
    aggregate_kernel<<<NN, 256>>>(h, src, b2, out);
}